// round 5
// baseline (speedup 1.0000x reference)
#include <cuda_runtime.h>
#include <cstdint>

#define NN    65536          // B*N nodes
#define EDG   1048576        // B*EPER edges
#define SLOTS 64             // max adjacency slots per node
#define C3    384
#define NHEAD 5
#define NCENT 15             // HEADS*KC

// ---------------- scratch (static __device__, no allocations) ----------------
__device__ int   d_in_cnt[NN];
__device__ int   d_out_cnt[NN];
__device__ int   d_in_list[NN * SLOTS];    // srcs grouped by dst
__device__ int   d_out_list[NN * SLOTS];   // dsts grouped by src
__device__ float d_m[(size_t)NN * 128];    // GEMM output per layer
__device__ float d_X[(size_t)NN * C3];     // [h1|h2|h3] post-relu
__device__ float d_Sf[(size_t)NN * 4];     // S per node (3 + pad)
__device__ float d_val[NN];                // softmax max value per node
__device__ int   d_amax[NN];               // argmax cluster per node
__device__ float d_outx[128 * 32];         // pooled features per graph
__device__ float d_csum[C3], d_csum2[C3];  // BN accumulators
__device__ float d_a[C3], d_bb[C3];        // BN affine: xn = a*x + bb
__device__ float d_knorm[NCENT];
__device__ float d_scal[8];                // 0 sumloss, 1 cnt0, 2 cnt1, 3 A0, 4 A1

// ---------------- kernels ----------------
__global__ void k_zero() {
    int i = blockIdx.x * 256 + threadIdx.x;
    if (i < NN) { d_in_cnt[i] = 0; d_out_cnt[i] = 0; }
    if (i < C3) { d_csum[i] = 0.f; d_csum2[i] = 0.f; }
    if (i < 8)  d_scal[i] = 0.f;
}

// edge_index arrives as int32 (harness downcasts int64 inputs).
__global__ void k_fill(const int* __restrict__ ei) {
    const int* src = ei;
    const int* dst = ei + EDG;
    for (int e = blockIdx.x * blockDim.x + threadIdx.x; e < EDG;
         e += gridDim.x * blockDim.x) {
        int s = src[e] & (NN - 1);       // defensive mask, indices are < NN
        int d = dst[e] & (NN - 1);
        int sl = atomicAdd(&d_in_cnt[d], 1);
        if (sl < SLOTS) d_in_list[d * SLOTS + sl] = s;
        int s2 = atomicAdd(&d_out_cnt[s], 1);
        if (s2 < SLOTS) d_out_list[s * SLOTS + s2] = d;
    }
}

// m = A(65536x128) @ W(128x128). BM=64, BN=128, BK=32 (4 chunks).
__global__ void k_gemm(const float* __restrict__ Aext, int mode,
                       const float* __restrict__ W) {
    __shared__ float As[64][33];
    __shared__ float Ws[32][128];
    const float* A;
    int lda;
    if (mode == 0)      { A = Aext;      lda = 128; }
    else if (mode == 1) { A = d_X;       lda = C3;  }
    else                { A = d_X + 128; lda = C3;  }

    int tid  = threadIdx.x;
    int row0 = blockIdx.x * 64;
    int tr   = tid >> 4;     // 0..15 (4 rows each)
    int tc   = tid & 15;     // 0..15 (8 cols each)

    float acc[4][8];
#pragma unroll
    for (int i = 0; i < 4; i++)
#pragma unroll
        for (int j = 0; j < 8; j++) acc[i][j] = 0.f;

    int ar  = tid >> 2;      // 0..63
    int ac8 = (tid & 3) * 8; // 0,8,16,24

    for (int kc = 0; kc < 4; kc++) {
        {
            const float* Arow = A + (size_t)(row0 + ar) * lda + kc * 32 + ac8;
            float4 v0 = *(const float4*)(Arow);
            float4 v1 = *(const float4*)(Arow + 4);
            float* dsp = &As[ar][ac8];
            dsp[0] = v0.x; dsp[1] = v0.y; dsp[2] = v0.z; dsp[3] = v0.w;
            dsp[4] = v1.x; dsp[5] = v1.y; dsp[6] = v1.z; dsp[7] = v1.w;
        }
#pragma unroll
        for (int i = 0; i < 4; i++) {
            int s   = tid + i * 256;       // 0..1023 float4 units
            int wr  = s >> 5;              // 0..31
            int wc4 = s & 31;              // 0..31
            *(float4*)&Ws[wr][wc4 * 4] =
                *(const float4*)(W + (size_t)(kc * 32 + wr) * 128 + wc4 * 4);
        }
        __syncthreads();

#pragma unroll
        for (int k = 0; k < 32; k++) {
            float4 w0 = *(const float4*)&Ws[k][tc * 8];
            float4 w1 = *(const float4*)&Ws[k][tc * 8 + 4];
#pragma unroll
            for (int i = 0; i < 4; i++) {
                float a = As[tr * 4 + i][k];
                acc[i][0] = fmaf(a, w0.x, acc[i][0]);
                acc[i][1] = fmaf(a, w0.y, acc[i][1]);
                acc[i][2] = fmaf(a, w0.z, acc[i][2]);
                acc[i][3] = fmaf(a, w0.w, acc[i][3]);
                acc[i][4] = fmaf(a, w1.x, acc[i][4]);
                acc[i][5] = fmaf(a, w1.y, acc[i][5]);
                acc[i][6] = fmaf(a, w1.z, acc[i][6]);
                acc[i][7] = fmaf(a, w1.w, acc[i][7]);
            }
        }
        __syncthreads();
    }
#pragma unroll
    for (int i = 0; i < 4; i++) {
        float* o = d_m + (size_t)(row0 + tr * 4 + i) * 128 + tc * 8;
        float4 u0, u1;
        u0.x = acc[i][0]; u0.y = acc[i][1]; u0.z = acc[i][2]; u0.w = acc[i][3];
        u1.x = acc[i][4]; u1.y = acc[i][5]; u1.z = acc[i][6]; u1.w = acc[i][7];
        *(float4*)o       = u0;
        *(float4*)(o + 4) = u1;
    }
}

// agg[dst] = relu(sum_{src in list(dst)} m[src] + b). One channel per thread,
// 128 channels per block, 32 nodes per block. BN partials in registers,
// one global atomicAdd per thread at the end.
__global__ void k_agg(const float* __restrict__ bias, int chBase) {
    __shared__ int s_idx[SLOTS];
    __shared__ int s_cnt;
    int ch = threadIdx.x;               // 0..127
    float b = bias[ch];
    float ch_sum = 0.f, ch_sq = 0.f;
    int n0 = blockIdx.x * 32;

    for (int t = 0; t < 32; t++) {
        int node = n0 + t;
        __syncthreads();
        if (ch == 0) {
            int c = d_in_cnt[node];
            s_cnt = c < SLOTS ? c : SLOTS;
        }
        if (ch < SLOTS) s_idx[ch] = d_in_list[(size_t)node * SLOTS + ch];
        __syncthreads();
        int cnt = s_cnt;
        float a = 0.f;
        for (int j = 0; j < cnt; j++)
            a += d_m[(size_t)s_idx[j] * 128 + ch];
        float o = fmaxf(a + b, 0.f);
        d_X[(size_t)node * C3 + chBase + ch] = o;
        ch_sum += o;
        ch_sq  = fmaf(o, o, ch_sq);
    }
    atomicAdd(&d_csum [chBase + ch], ch_sum);
    atomicAdd(&d_csum2[chBase + ch], ch_sq);
}

// BN affine + centroid norms
__global__ void k_bn(const float* __restrict__ gamma, const float* __restrict__ beta,
                     const float* __restrict__ kmat) {
    int t = threadIdx.x;
    if (t < C3) {
        float mu  = d_csum [t] * (1.f / NN);
        float var = d_csum2[t] * (1.f / NN) - mu * mu;
        float a   = gamma[t] * rsqrtf(var + 1e-5f);
        d_a[t]  = a;
        d_bb[t] = beta[t] - mu * a;
    }
    int wid = t >> 5, lane = t & 31;
    if (wid < NCENT) {
        float s = 0.f;
        for (int c = lane; c < C3; c += 32) {
            float v = kmat[wid * C3 + c];
            s = fmaf(v, v, s);
        }
#pragma unroll
        for (int off = 16; off; off >>= 1) s += __shfl_xor_sync(0xffffffffu, s, off);
        if (lane == 0) d_knorm[wid] = s;
    }
}

// per-node soft assignment S (sum over heads of normalized t-dist)
__global__ void k_dist(const float* __restrict__ kmat) {
    __shared__ float k2s[NCENT * C3];
    __shared__ float a_s[C3], bb_s[C3];
    __shared__ float kn_s[NCENT];
    for (int i = threadIdx.x; i < NCENT * C3; i += 256) k2s[i] = kmat[i];
    for (int i = threadIdx.x; i < C3; i += 256) { a_s[i] = d_a[i]; bb_s[i] = d_bb[i]; }
    if (threadIdx.x < NCENT) kn_s[threadIdx.x] = d_knorm[threadIdx.x];
    __syncthreads();

    int wid = threadIdx.x >> 5, lane = threadIdx.x & 31;
    int warpG = blockIdx.x * 8 + wid;
    int totW  = gridDim.x * 8;

    float av[12], bv[12];
#pragma unroll
    for (int u = 0; u < 12; u++) {
        av[u] = a_s [lane * 12 + u];
        bv[u] = bb_s[lane * 12 + u];
    }

    for (int node = warpG; node < NN; node += totW) {
        const float* xr = d_X + (size_t)node * C3 + lane * 12;
        float xn[12];
#pragma unroll
        for (int u = 0; u < 12; u++) xn[u] = fmaf(xr[u], av[u], bv[u]);

        float red[16];
        float nrm = 0.f;
#pragma unroll
        for (int u = 0; u < 12; u++) nrm = fmaf(xn[u], xn[u], nrm);
        red[15] = nrm;
#pragma unroll
        for (int j = 0; j < NCENT; j++) {
            const float* kr = k2s + j * C3 + lane * 12;
            float d = 0.f;
#pragma unroll
            for (int u = 0; u < 12; u++) d = fmaf(kr[u], xn[u], d);
            red[j] = d;
        }
#pragma unroll
        for (int off = 16; off; off >>= 1)
#pragma unroll
            for (int r = 0; r < 16; r++)
                red[r] += __shfl_xor_sync(0xffffffffu, red[r], off);

        if (lane == 0) {
            float nt = red[15];
            float S0 = 0.f, S1 = 0.f, S2 = 0.f;
#pragma unroll
            for (int h = 0; h < NHEAD; h++) {
                float dd[3];
#pragma unroll
                for (int kk = 0; kk < 3; kk++) {
                    int j = h * 3 + kk;
                    float d2 = fmaxf(kn_s[j] + nt - 2.f * red[j], 0.f);
                    dd[kk] = 1.f / (1.f + d2);
                }
                float inv = 1.f / (dd[0] + dd[1] + dd[2]);
                S0 += dd[0] * inv; S1 += dd[1] * inv; S2 += dd[2] * inv;
            }
            float* o = d_Sf + (size_t)node * 4;
            o[0] = S0; o[1] = S1; o[2] = S2; o[3] = 0.f;
        }
    }
}

// Sagg gather (by src), deg, softmax, argmax, loss contributions. y is int32.
__global__ void k_S2(const int* __restrict__ y) {
    __shared__ float rs[5][256];
    int i = blockIdx.x * 256 + threadIdx.x;
    float sl = 0.f, c0 = 0.f, c1 = 0.f, A0 = 0.f, A1 = 0.f;
    {
        int oc  = d_out_cnt[i];
        int cnt = oc < SLOTS ? oc : SLOTS;
        const int* lst = d_out_list + (size_t)i * SLOTS;
        const float4* Sf4 = (const float4*)d_Sf;
        float r0 = 0.f, r1 = 0.f, r2 = 0.f;
        for (int j = 0; j < cnt; j++) {
            float4 s = Sf4[lst[j]];
            r0 += s.x; r1 += s.y; r2 += s.z;
        }
        int ic = d_in_cnt[i];
        float deg = 0.5f * (float)(oc + ic);
        if (deg == 0.f) deg = 1.f;
        float inv = 1.f / deg;
        r0 *= inv; r1 *= inv; r2 *= inv;
        int am = 0; float mx = r0;
        if (r1 > mx) { am = 1; mx = r1; }
        if (r2 > mx) { am = 2; mx = r2; }
        float val = 1.f / (expf(r0 - mx) + expf(r1 - mx) + expf(r2 - mx));
        d_amax[i] = am;
        d_val[i]  = val;
        if (am < 2) {
            sl = val;
            int yb = y[i >> 9];
            float ce = log1pf(expf(val)) - (yb == am ? val : 0.f);
            if (yb == 0) { c0 = 1.f; A0 = ce; } else { c1 = 1.f; A1 = ce; }
        }
    }
    int t = threadIdx.x;
    rs[0][t] = sl; rs[1][t] = c0; rs[2][t] = c1; rs[3][t] = A0; rs[4][t] = A1;
    __syncthreads();
    for (int s = 128; s > 0; s >>= 1) {
        if (t < s) {
#pragma unroll
            for (int r = 0; r < 5; r++) rs[r][t] += rs[r][t + s];
        }
        __syncthreads();
    }
    if (t < 5) atomicAdd(&d_scal[t], rs[t][0]);
}

// per-graph pooling xp[k,c] = sum_n Sfin * Xn, then @ lin_pool_W -> outx[b,2,16]
__global__ void k_pool(const float* __restrict__ Wp) {
    int b = blockIdx.x, t = threadIdx.x;
    __shared__ float vals[512];
    __shared__ int   ams[512];
    __shared__ float xp[2][C3];
    for (int n = t; n < 512; n += 384) {
        vals[n] = d_val [b * 512 + n];
        ams[n]  = d_amax[b * 512 + n];
    }
    __syncthreads();
    float ac = d_a[t], bc = d_bb[t];
    float acc0 = 0.f, acc1 = 0.f;
    const float* Xb = d_X + (size_t)b * 512 * C3 + t;
    for (int n = 0; n < 512; n++) {
        float x  = Xb[(size_t)n * C3];
        float v  = vals[n];
        int   am = ams[n];
        float xn = fmaf(x, ac, bc);
        if (am == 0)      acc0 = fmaf(v, xn, acc0);
        else if (am == 1) acc1 = fmaf(v, xn, acc1);
    }
    xp[0][t] = acc0; xp[1][t] = acc1;
    __syncthreads();
    if (t < 32) {
        int kk = t >> 4, o = t & 15;
        float s = 0.f;
        for (int c = 0; c < C3; c++) s = fmaf(xp[kk][c], Wp[c * 16 + o], s);
        d_outx[b * 32 + kk * 16 + o] = s;
    }
}

// classification head: relu(xf@W1+b1) @ W2 + b2, log_softmax
__global__ void k_head(const float* __restrict__ W1, const float* __restrict__ b1,
                       const float* __restrict__ W2, const float* __restrict__ b2,
                       float* __restrict__ out) {
    int b = blockIdx.x, t = threadIdx.x;
    __shared__ float xf[32];
    __shared__ float h[128];
    __shared__ float lg[2];
    if (t < 32) xf[t] = d_outx[b * 32 + t];
    __syncthreads();
    float acc = b1[t];
#pragma unroll
    for (int i = 0; i < 32; i++) acc = fmaf(xf[i], W1[i * 128 + t], acc);
    h[t] = fmaxf(acc, 0.f);
    __syncthreads();
    if (t < 64) {
        int c = t >> 5, l = t & 31;
        float p = 0.f;
        for (int j = l; j < 128; j += 32) p = fmaf(h[j], W2[j * 2 + c], p);
#pragma unroll
        for (int off = 16; off; off >>= 1) p += __shfl_xor_sync(0xffffffffu, p, off);
        if (l == 0) lg[c] = p + b2[c];
    }
    __syncthreads();
    if (t == 0) {
        float m   = fmaxf(lg[0], lg[1]);
        float lse = m + logf(expf(lg[0] - m) + expf(lg[1] - m));
        out[b * 2 + 0] = lg[0] - lse;
        out[b * 2 + 1] = lg[1] - lse;
    }
}

__global__ void k_loss(float* __restrict__ out, int idx) {
    float sl = d_scal[0], c0 = d_scal[1], c1 = d_scal[2];
    float A0 = d_scal[3], A1 = d_scal[4];
    float bc0 = 1.f + c0, bc1 = 1.f + c1;
    float wm  = fmaxf(bc0, bc1);
    float w0  = wm / (bc0 + 0.001f), w1 = wm / (bc1 + 0.001f);
    float den = fmaxf(w0 * c0 + w1 * c1, 1e-12f);
    float cel = (w0 * A0 + w1 * A1) / den;
    out[idx] = 10.f * cel + 0.01f * (sl * (1.f / 128.f));
}

// ---------------- launch ----------------
extern "C" void kernel_launch(void* const* d_in, const int* in_sizes, int n_in,
                              void* d_out, int out_size) {
    const float* x     = (const float*)d_in[0];
    const int*   ei    = (const int*)d_in[1];     // int64 downcast to int32 by harness
    const int*   y     = (const int*)d_in[2];     // int64 downcast to int32 by harness
    const float* W1    = (const float*)d_in[3];
    const float* b1    = (const float*)d_in[4];
    const float* W2    = (const float*)d_in[5];
    const float* b2    = (const float*)d_in[6];
    const float* W3    = (const float*)d_in[7];
    const float* b3    = (const float*)d_in[8];
    const float* gamma = (const float*)d_in[9];
    const float* beta  = (const float*)d_in[10];
    const float* kmat  = (const float*)d_in[11];
    const float* Wp    = (const float*)d_in[12];
    const float* l1W   = (const float*)d_in[13];
    const float* l1b   = (const float*)d_in[14];
    const float* l2W   = (const float*)d_in[15];
    const float* l2b   = (const float*)d_in[16];
    float* out = (float*)d_out;

    k_zero<<<256, 256>>>();
    k_fill<<<2048, 256>>>(ei);

    k_gemm<<<1024, 256>>>(x, 0, W1);
    k_agg<<<2048, 128>>>(b1, 0);
    k_gemm<<<1024, 256>>>(x, 1, W2);
    k_agg<<<2048, 128>>>(b2, 128);
    k_gemm<<<1024, 256>>>(x, 2, W3);
    k_agg<<<2048, 128>>>(b3, 256);

    k_bn<<<1, 512>>>(gamma, beta, kmat);
    k_dist<<<2048, 256>>>(kmat);
    k_S2<<<256, 256>>>(y);
    k_pool<<<128, 384>>>(Wp);
    k_head<<<128, 128>>>(l1W, l1b, l2W, l2b, out);
    k_loss<<<1, 1>>>(out, out_size - 1);
}

// round 6
// speedup vs baseline: 1.2208x; 1.2208x over previous
#include <cuda_runtime.h>
#include <cstdint>

#define NN    65536          // B*N nodes
#define EDG   1048576        // B*EPER edges
#define SLOTS 64             // max adjacency slots per node
#define C3    384
#define NHEAD 5
#define NCENT 15             // HEADS*KC

// ---------------- scratch (static __device__, no allocations) ----------------
__device__ int   d_in_cnt[NN];
__device__ int   d_out_cnt[NN];
__device__ int   d_in_list[NN * SLOTS];    // srcs grouped by dst
__device__ int   d_out_list[NN * SLOTS];   // dsts grouped by src
__device__ float d_m[(size_t)NN * 128];    // GEMM output per layer
__device__ float d_X[(size_t)NN * C3];     // [h1|h2|h3] post-relu
__device__ float d_Sf[(size_t)NN * 4];     // S per node (3 + pad)
__device__ float d_val[NN];                // softmax max value per node
__device__ int   d_amax[NN];               // argmax cluster per node
__device__ float d_outx[128 * 32];         // pooled features per graph
__device__ float d_csum[C3], d_csum2[C3];  // BN accumulators
__device__ float d_a[C3], d_bb[C3];        // BN affine: xn = a*x + bb
__device__ float d_knorm[NCENT];
__device__ float d_scal[8];                // 0 sumloss, 1 cnt0, 2 cnt1, 3 A0, 4 A1

// ---------------- packed f32x2 helpers (Blackwell FFMA2) ----------------
__device__ __forceinline__ unsigned long long pack2(float lo, float hi) {
    unsigned long long r;
    asm("mov.b64 %0, {%1, %2};" : "=l"(r) : "f"(lo), "f"(hi));
    return r;
}
__device__ __forceinline__ void ffma2(unsigned long long& acc,
                                      unsigned long long a, unsigned long long b) {
    asm("fma.rn.f32x2 %0, %1, %2, %0;" : "+l"(acc) : "l"(a), "l"(b));
}

// ---------------- kernels ----------------
__global__ void k_zero() {
    int i = blockIdx.x * 256 + threadIdx.x;
    if (i < NN) { d_in_cnt[i] = 0; d_out_cnt[i] = 0; }
    if (i < C3) { d_csum[i] = 0.f; d_csum2[i] = 0.f; }
    if (i < 8)  d_scal[i] = 0.f;
}

// edge_index arrives as int32 (harness downcasts int64 inputs).
__global__ void k_fill(const int* __restrict__ ei) {
    const int* src = ei;
    const int* dst = ei + EDG;
    for (int e = blockIdx.x * blockDim.x + threadIdx.x; e < EDG;
         e += gridDim.x * blockDim.x) {
        int s = src[e] & (NN - 1);
        int d = dst[e] & (NN - 1);
        int sl = atomicAdd(&d_in_cnt[d], 1);
        if (sl < SLOTS) d_in_list[d * SLOTS + sl] = s;
        int s2 = atomicAdd(&d_out_cnt[s], 1);
        if (s2 < SLOTS) d_out_list[s * SLOTS + s2] = d;
    }
}

// m = A(65536x128) @ W(128x128). BM=64, BN=128, BK=32. f32x2 packed FMA.
__global__ void k_gemm(const float* __restrict__ Aext, int mode,
                       const float* __restrict__ W) {
    __shared__ float As[64][33];
    __shared__ float Ws[32][128];
    const float* A;
    int lda;
    if (mode == 0)      { A = Aext;      lda = 128; }
    else if (mode == 1) { A = d_X;       lda = C3;  }
    else                { A = d_X + 128; lda = C3;  }

    int tid  = threadIdx.x;
    int row0 = blockIdx.x * 64;
    int tr   = tid >> 4;     // 0..15 (4 rows each)
    int tc   = tid & 15;     // 0..15 (8 cols = 4 f32x2 pairs each)

    unsigned long long acc[4][4];
#pragma unroll
    for (int i = 0; i < 4; i++)
#pragma unroll
        for (int j = 0; j < 4; j++) acc[i][j] = 0ull;

    int ar  = tid >> 2;      // 0..63
    int ac8 = (tid & 3) * 8; // 0,8,16,24

    for (int kc = 0; kc < 4; kc++) {
        {
            const float* Arow = A + (size_t)(row0 + ar) * lda + kc * 32 + ac8;
            float4 v0 = *(const float4*)(Arow);
            float4 v1 = *(const float4*)(Arow + 4);
            float* dsp = &As[ar][ac8];
            dsp[0] = v0.x; dsp[1] = v0.y; dsp[2] = v0.z; dsp[3] = v0.w;
            dsp[4] = v1.x; dsp[5] = v1.y; dsp[6] = v1.z; dsp[7] = v1.w;
        }
#pragma unroll
        for (int i = 0; i < 4; i++) {
            int s   = tid + i * 256;
            int wr  = s >> 5;
            int wc4 = s & 31;
            *(float4*)&Ws[wr][wc4 * 4] =
                *(const float4*)(W + (size_t)(kc * 32 + wr) * 128 + wc4 * 4);
        }
        __syncthreads();

#pragma unroll
        for (int k = 0; k < 32; k++) {
            ulonglong2 b01 = *(const ulonglong2*)&Ws[k][tc * 8];
            ulonglong2 b23 = *(const ulonglong2*)&Ws[k][tc * 8 + 4];
#pragma unroll
            for (int i = 0; i < 4; i++) {
                float a = As[tr * 4 + i][k];
                unsigned long long aa = pack2(a, a);
                ffma2(acc[i][0], aa, b01.x);
                ffma2(acc[i][1], aa, b01.y);
                ffma2(acc[i][2], aa, b23.x);
                ffma2(acc[i][3], aa, b23.y);
            }
        }
        __syncthreads();
    }
#pragma unroll
    for (int i = 0; i < 4; i++) {
        float* o = d_m + (size_t)(row0 + tr * 4 + i) * 128 + tc * 8;
        ulonglong2 u0, u1;
        u0.x = acc[i][0]; u0.y = acc[i][1];
        u1.x = acc[i][2]; u1.y = acc[i][3];
        *(ulonglong2*)o       = u0;
        *(ulonglong2*)(o + 4) = u1;
    }
}

// agg[dst] = relu(sum_{src in list(dst)} m[src] + b). Warp per node, float4
// per lane, shfl-broadcast indices, 4 independent accumulators (MLP=4).
// BN partials: registers -> smem tree (per-warp slices) -> global atomics.
__global__ void k_agg(const float* __restrict__ bias, int chBase) {
    __shared__ float bsum[8][128];
    __shared__ float bsq [8][128];
    int wid = threadIdx.x >> 5, lane = threadIdx.x & 31;
    int warpG = blockIdx.x * 8 + wid;
    int totW  = gridDim.x * 8;          // 16384 warps, 4 nodes each
    float4 bv = *(const float4*)(bias + lane * 4);
    const float4* m4 = (const float4*)d_m;
    float s0 = 0, s1 = 0, s2 = 0, s3 = 0, q0 = 0, q1 = 0, q2 = 0, q3 = 0;

    for (int node = warpG; node < NN; node += totW) {
        int raw = d_in_cnt[node];
        int cnt = raw < SLOTS ? raw : SLOTS;
        const int* lst = d_in_list + (size_t)node * SLOTS;
        int i0 = (lane < cnt)      ? lst[lane]      : 0;
        int i1 = (32 + lane < cnt) ? lst[32 + lane] : 0;

        float4 a0 = {0,0,0,0}, a1 = {0,0,0,0}, a2 = {0,0,0,0}, a3 = {0,0,0,0};
        int c1 = cnt < 32 ? cnt : 32;
        int j = 0;
        for (; j + 4 <= c1; j += 4) {
            int t0 = __shfl_sync(0xffffffffu, i0, j);
            int t1 = __shfl_sync(0xffffffffu, i0, j + 1);
            int t2 = __shfl_sync(0xffffffffu, i0, j + 2);
            int t3 = __shfl_sync(0xffffffffu, i0, j + 3);
            float4 v0 = m4[(size_t)t0 * 32 + lane];
            float4 v1 = m4[(size_t)t1 * 32 + lane];
            float4 v2 = m4[(size_t)t2 * 32 + lane];
            float4 v3 = m4[(size_t)t3 * 32 + lane];
            a0.x += v0.x; a0.y += v0.y; a0.z += v0.z; a0.w += v0.w;
            a1.x += v1.x; a1.y += v1.y; a1.z += v1.z; a1.w += v1.w;
            a2.x += v2.x; a2.y += v2.y; a2.z += v2.z; a2.w += v2.w;
            a3.x += v3.x; a3.y += v3.y; a3.z += v3.z; a3.w += v3.w;
        }
        for (; j < c1; j++) {
            int t0 = __shfl_sync(0xffffffffu, i0, j);
            float4 v0 = m4[(size_t)t0 * 32 + lane];
            a0.x += v0.x; a0.y += v0.y; a0.z += v0.z; a0.w += v0.w;
        }
        for (int j2 = 32; j2 < cnt; j2++) {
            int t0 = __shfl_sync(0xffffffffu, i1, j2 - 32);
            float4 v0 = m4[(size_t)t0 * 32 + lane];
            a1.x += v0.x; a1.y += v0.y; a1.z += v0.z; a1.w += v0.w;
        }
        float4 o;
        o.x = fmaxf(a0.x + a1.x + a2.x + a3.x + bv.x, 0.f);
        o.y = fmaxf(a0.y + a1.y + a2.y + a3.y + bv.y, 0.f);
        o.z = fmaxf(a0.z + a1.z + a2.z + a3.z + bv.z, 0.f);
        o.w = fmaxf(a0.w + a1.w + a2.w + a3.w + bv.w, 0.f);
        *(float4*)(d_X + (size_t)node * C3 + chBase + lane * 4) = o;
        s0 += o.x; s1 += o.y; s2 += o.z; s3 += o.w;
        q0 = fmaf(o.x, o.x, q0); q1 = fmaf(o.y, o.y, q1);
        q2 = fmaf(o.z, o.z, q2); q3 = fmaf(o.w, o.w, q3);
    }
    bsum[wid][lane * 4 + 0] = s0; bsum[wid][lane * 4 + 1] = s1;
    bsum[wid][lane * 4 + 2] = s2; bsum[wid][lane * 4 + 3] = s3;
    bsq [wid][lane * 4 + 0] = q0; bsq [wid][lane * 4 + 1] = q1;
    bsq [wid][lane * 4 + 2] = q2; bsq [wid][lane * 4 + 3] = q3;
    __syncthreads();
    if (threadIdx.x < 128) {
        int ch = threadIdx.x;
        float ts = 0.f, tq = 0.f;
#pragma unroll
        for (int w = 0; w < 8; w++) { ts += bsum[w][ch]; tq += bsq[w][ch]; }
        atomicAdd(&d_csum [chBase + ch], ts);
        atomicAdd(&d_csum2[chBase + ch], tq);
    }
}

// BN affine + centroid norms
__global__ void k_bn(const float* __restrict__ gamma, const float* __restrict__ beta,
                     const float* __restrict__ kmat) {
    int t = threadIdx.x;
    if (t < C3) {
        float mu  = d_csum [t] * (1.f / NN);
        float var = d_csum2[t] * (1.f / NN) - mu * mu;
        float a   = gamma[t] * rsqrtf(var + 1e-5f);
        d_a[t]  = a;
        d_bb[t] = beta[t] - mu * a;
    }
    int wid = t >> 5, lane = t & 31;
    if (wid < NCENT) {
        float s = 0.f;
        for (int c = lane; c < C3; c += 32) {
            float v = kmat[wid * C3 + c];
            s = fmaf(v, v, s);
        }
#pragma unroll
        for (int off = 16; off; off >>= 1) s += __shfl_xor_sync(0xffffffffu, s, off);
        if (lane == 0) d_knorm[wid] = s;
    }
}

// per-node soft assignment S (sum over heads of normalized t-dist)
__global__ void k_dist(const float* __restrict__ kmat) {
    __shared__ float k2s[NCENT * C3];
    __shared__ float a_s[C3], bb_s[C3];
    __shared__ float kn_s[NCENT];
    for (int i = threadIdx.x; i < NCENT * C3; i += 256) k2s[i] = kmat[i];
    for (int i = threadIdx.x; i < C3; i += 256) { a_s[i] = d_a[i]; bb_s[i] = d_bb[i]; }
    if (threadIdx.x < NCENT) kn_s[threadIdx.x] = d_knorm[threadIdx.x];
    __syncthreads();

    int wid = threadIdx.x >> 5, lane = threadIdx.x & 31;
    int warpG = blockIdx.x * 8 + wid;
    int totW  = gridDim.x * 8;

    float av[12], bv[12];
#pragma unroll
    for (int u = 0; u < 12; u++) {
        av[u] = a_s [lane * 12 + u];
        bv[u] = bb_s[lane * 12 + u];
    }

    for (int node = warpG; node < NN; node += totW) {
        const float* xr = d_X + (size_t)node * C3 + lane * 12;
        float xn[12];
#pragma unroll
        for (int u = 0; u < 12; u++) xn[u] = fmaf(xr[u], av[u], bv[u]);

        float red[16];
        float nrm = 0.f;
#pragma unroll
        for (int u = 0; u < 12; u++) nrm = fmaf(xn[u], xn[u], nrm);
        red[15] = nrm;
#pragma unroll
        for (int j = 0; j < NCENT; j++) {
            const float* kr = k2s + j * C3 + lane * 12;
            float d = 0.f;
#pragma unroll
            for (int u = 0; u < 12; u++) d = fmaf(kr[u], xn[u], d);
            red[j] = d;
        }
#pragma unroll
        for (int off = 16; off; off >>= 1)
#pragma unroll
            for (int r = 0; r < 16; r++)
                red[r] += __shfl_xor_sync(0xffffffffu, red[r], off);

        if (lane == 0) {
            float nt = red[15];
            float S0 = 0.f, S1 = 0.f, S2 = 0.f;
#pragma unroll
            for (int h = 0; h < NHEAD; h++) {
                float dd[3];
#pragma unroll
                for (int kk = 0; kk < 3; kk++) {
                    int j = h * 3 + kk;
                    float d2 = fmaxf(kn_s[j] + nt - 2.f * red[j], 0.f);
                    dd[kk] = 1.f / (1.f + d2);
                }
                float inv = 1.f / (dd[0] + dd[1] + dd[2]);
                S0 += dd[0] * inv; S1 += dd[1] * inv; S2 += dd[2] * inv;
            }
            float* o = d_Sf + (size_t)node * 4;
            o[0] = S0; o[1] = S1; o[2] = S2; o[3] = 0.f;
        }
    }
}

// Sagg gather (by src), deg, softmax, argmax, loss contributions. y is int32.
__global__ void k_S2(const int* __restrict__ y) {
    __shared__ float rs[5][256];
    int i = blockIdx.x * 256 + threadIdx.x;
    float sl = 0.f, c0 = 0.f, c1 = 0.f, A0 = 0.f, A1 = 0.f;
    {
        int oc  = d_out_cnt[i];
        int cnt = oc < SLOTS ? oc : SLOTS;
        const int* lst = d_out_list + (size_t)i * SLOTS;
        const float4* Sf4 = (const float4*)d_Sf;
        float r0 = 0.f, r1 = 0.f, r2 = 0.f;
        for (int j = 0; j < cnt; j++) {
            float4 s = Sf4[lst[j]];
            r0 += s.x; r1 += s.y; r2 += s.z;
        }
        int ic = d_in_cnt[i];
        float deg = 0.5f * (float)(oc + ic);
        if (deg == 0.f) deg = 1.f;
        float inv = 1.f / deg;
        r0 *= inv; r1 *= inv; r2 *= inv;
        int am = 0; float mx = r0;
        if (r1 > mx) { am = 1; mx = r1; }
        if (r2 > mx) { am = 2; mx = r2; }
        float val = 1.f / (expf(r0 - mx) + expf(r1 - mx) + expf(r2 - mx));
        d_amax[i] = am;
        d_val[i]  = val;
        if (am < 2) {
            sl = val;
            int yb = y[i >> 9];
            float ce = log1pf(expf(val)) - (yb == am ? val : 0.f);
            if (yb == 0) { c0 = 1.f; A0 = ce; } else { c1 = 1.f; A1 = ce; }
        }
    }
    int t = threadIdx.x;
    rs[0][t] = sl; rs[1][t] = c0; rs[2][t] = c1; rs[3][t] = A0; rs[4][t] = A1;
    __syncthreads();
    for (int s = 128; s > 0; s >>= 1) {
        if (t < s) {
#pragma unroll
            for (int r = 0; r < 5; r++) rs[r][t] += rs[r][t + s];
        }
        __syncthreads();
    }
    if (t < 5) atomicAdd(&d_scal[t], rs[t][0]);
}

// per-graph pooling xp[k,c] = sum_n Sfin * Xn, then @ lin_pool_W -> outx[b,2,16]
__global__ void k_pool(const float* __restrict__ Wp) {
    int b = blockIdx.x, t = threadIdx.x;
    __shared__ float vals[512];
    __shared__ int   ams[512];
    __shared__ float xp[2][C3];
    for (int n = t; n < 512; n += 384) {
        vals[n] = d_val [b * 512 + n];
        ams[n]  = d_amax[b * 512 + n];
    }
    __syncthreads();
    float ac = d_a[t], bc = d_bb[t];
    float acc0 = 0.f, acc1 = 0.f;
    const float* Xb = d_X + (size_t)b * 512 * C3 + t;
    for (int n = 0; n < 512; n++) {
        float x  = Xb[(size_t)n * C3];
        float v  = vals[n];
        int   am = ams[n];
        float xn = fmaf(x, ac, bc);
        if (am == 0)      acc0 = fmaf(v, xn, acc0);
        else if (am == 1) acc1 = fmaf(v, xn, acc1);
    }
    xp[0][t] = acc0; xp[1][t] = acc1;
    __syncthreads();
    if (t < 32) {
        int kk = t >> 4, o = t & 15;
        float s = 0.f;
        for (int c = 0; c < C3; c++) s = fmaf(xp[kk][c], Wp[c * 16 + o], s);
        d_outx[b * 32 + kk * 16 + o] = s;
    }
}

// classification head: relu(xf@W1+b1) @ W2 + b2, log_softmax
__global__ void k_head(const float* __restrict__ W1, const float* __restrict__ b1,
                       const float* __restrict__ W2, const float* __restrict__ b2,
                       float* __restrict__ out) {
    int b = blockIdx.x, t = threadIdx.x;
    __shared__ float xf[32];
    __shared__ float h[128];
    __shared__ float lg[2];
    if (t < 32) xf[t] = d_outx[b * 32 + t];
    __syncthreads();
    float acc = b1[t];
#pragma unroll
    for (int i = 0; i < 32; i++) acc = fmaf(xf[i], W1[i * 128 + t], acc);
    h[t] = fmaxf(acc, 0.f);
    __syncthreads();
    if (t < 64) {
        int c = t >> 5, l = t & 31;
        float p = 0.f;
        for (int j = l; j < 128; j += 32) p = fmaf(h[j], W2[j * 2 + c], p);
#pragma unroll
        for (int off = 16; off; off >>= 1) p += __shfl_xor_sync(0xffffffffu, p, off);
        if (l == 0) lg[c] = p + b2[c];
    }
    __syncthreads();
    if (t == 0) {
        float m   = fmaxf(lg[0], lg[1]);
        float lse = m + logf(expf(lg[0] - m) + expf(lg[1] - m));
        out[b * 2 + 0] = lg[0] - lse;
        out[b * 2 + 1] = lg[1] - lse;
    }
}

__global__ void k_loss(float* __restrict__ out, int idx) {
    float sl = d_scal[0], c0 = d_scal[1], c1 = d_scal[2];
    float A0 = d_scal[3], A1 = d_scal[4];
    float bc0 = 1.f + c0, bc1 = 1.f + c1;
    float wm  = fmaxf(bc0, bc1);
    float w0  = wm / (bc0 + 0.001f), w1 = wm / (bc1 + 0.001f);
    float den = fmaxf(w0 * c0 + w1 * c1, 1e-12f);
    float cel = (w0 * A0 + w1 * A1) / den;
    out[idx] = 10.f * cel + 0.01f * (sl * (1.f / 128.f));
}

// ---------------- launch ----------------
extern "C" void kernel_launch(void* const* d_in, const int* in_sizes, int n_in,
                              void* d_out, int out_size) {
    const float* x     = (const float*)d_in[0];
    const int*   ei    = (const int*)d_in[1];
    const int*   y     = (const int*)d_in[2];
    const float* W1    = (const float*)d_in[3];
    const float* b1    = (const float*)d_in[4];
    const float* W2    = (const float*)d_in[5];
    const float* b2    = (const float*)d_in[6];
    const float* W3    = (const float*)d_in[7];
    const float* b3    = (const float*)d_in[8];
    const float* gamma = (const float*)d_in[9];
    const float* beta  = (const float*)d_in[10];
    const float* kmat  = (const float*)d_in[11];
    const float* Wp    = (const float*)d_in[12];
    const float* l1W   = (const float*)d_in[13];
    const float* l1b   = (const float*)d_in[14];
    const float* l2W   = (const float*)d_in[15];
    const float* l2b   = (const float*)d_in[16];
    float* out = (float*)d_out;

    k_zero<<<256, 256>>>();
    k_fill<<<2048, 256>>>(ei);

    k_gemm<<<1024, 256>>>(x, 0, W1);
    k_agg<<<2048, 256>>>(b1, 0);
    k_gemm<<<1024, 256>>>(x, 1, W2);
    k_agg<<<2048, 256>>>(b2, 128);
    k_gemm<<<1024, 256>>>(x, 2, W3);
    k_agg<<<2048, 256>>>(b3, 256);

    k_bn<<<1, 512>>>(gamma, beta, kmat);
    k_dist<<<2048, 256>>>(kmat);
    k_S2<<<256, 256>>>(y);
    k_pool<<<128, 384>>>(Wp);
    k_head<<<128, 128>>>(l1W, l1b, l2W, l2b, out);
    k_loss<<<1, 1>>>(out, out_size - 1);
}

// round 7
// speedup vs baseline: 1.2697x; 1.0400x over previous
#include <cuda_runtime.h>
#include <cstdint>

#define NN    65536          // B*N nodes
#define EDG   1048576        // B*EPER edges
#define SLOTS 64             // max adjacency slots per node
#define C3    384
#define NHEAD 5
#define NCENT 15             // HEADS*KC

// ---------------- scratch (static __device__, no allocations) ----------------
__device__ int   d_in_cnt[NN];
__device__ int   d_out_cnt[NN];
__device__ int   d_in_list[NN * SLOTS];    // srcs grouped by dst
__device__ int   d_out_list[NN * SLOTS];   // dsts grouped by src
__device__ float d_m[(size_t)NN * 128];    // GEMM output per layer
__device__ float d_X[(size_t)NN * C3];     // [h1|h2|h3] post-relu
__device__ float d_Sf[(size_t)NN * 4];     // S per node (3 + pad)
__device__ float d_val[NN];                // softmax max value per node
__device__ int   d_amax[NN];               // argmax cluster per node
__device__ float d_outx[128 * 32];         // pooled features per graph
__device__ float d_csum[C3], d_csum2[C3];  // BN accumulators
__device__ float d_a[C3], d_bb[C3];        // BN affine: xn = a*x + bb
__device__ float d_knorm[NCENT];
__device__ float d_scal[8];                // 0 sumloss, 1 cnt0, 2 cnt1, 3 A0, 4 A1

// ---------------- packed f32x2 helpers (Blackwell FFMA2) ----------------
__device__ __forceinline__ unsigned long long pack2(float lo, float hi) {
    unsigned long long r;
    asm("mov.b64 %0, {%1, %2};" : "=l"(r) : "f"(lo), "f"(hi));
    return r;
}
__device__ __forceinline__ void ffma2(unsigned long long& acc,
                                      unsigned long long a, unsigned long long b) {
    asm("fma.rn.f32x2 %0, %1, %2, %0;" : "+l"(acc) : "l"(a), "l"(b));
}

// ---------------- kernels ----------------
__global__ void k_zero1() {
    int i = blockIdx.x * 256 + threadIdx.x;
    if (i < NN) { d_in_cnt[i] = 0; d_out_cnt[i] = 0; }
}
__global__ void k_zero2() {
    int i = blockIdx.x * 256 + threadIdx.x;
    if (i < C3) { d_csum[i] = 0.f; d_csum2[i] = 0.f; }
    if (i < 8)  d_scal[i] = 0.f;
}

// edge_index arrives as int32 (harness downcasts int64 inputs).
__global__ void k_fill(const int* __restrict__ ei) {
    const int* src = ei;
    const int* dst = ei + EDG;
    for (int e = blockIdx.x * blockDim.x + threadIdx.x; e < EDG;
         e += gridDim.x * blockDim.x) {
        int s = src[e] & (NN - 1);
        int d = dst[e] & (NN - 1);
        int sl = atomicAdd(&d_in_cnt[d], 1);
        if (sl < SLOTS) d_in_list[d * SLOTS + sl] = s;
        int s2 = atomicAdd(&d_out_cnt[s], 1);
        if (s2 < SLOTS) d_out_list[s * SLOTS + s2] = d;
    }
}

// m = A(65536x128) @ W(128x128). BM=128, BN=128, BK=16, 8x8 per-thread tile,
// f32x2 packed FMA. 1.0 B smem per MAC -> smem/FMA balanced.
__global__ void __launch_bounds__(256, 2)
k_gemm(const float* __restrict__ Aext, int mode, const float* __restrict__ W) {
    __shared__ float AsT[16][132];   // [k][row], transposed A chunk
    __shared__ float Ws [16][132];   // [k][col]
    const float* A;
    int lda;
    if (mode == 0)      { A = Aext;      lda = 128; }
    else if (mode == 1) { A = d_X;       lda = C3;  }
    else                { A = d_X + 128; lda = C3;  }

    int tid  = threadIdx.x;
    int row0 = blockIdx.x * 128;
    int tr   = tid >> 4;     // 0..15 -> rows tr*8..tr*8+7
    int tc   = tid & 15;     // 0..15 -> cols tc*8..tc*8+7

    unsigned long long acc[8][4];
#pragma unroll
    for (int i = 0; i < 8; i++)
#pragma unroll
        for (int j = 0; j < 4; j++) acc[i][j] = 0ull;

    int lr = tid >> 1;          // 0..127: row this thread loads
    int lk = (tid & 1) * 8;     // 0 or 8: k-offset within chunk

    for (int kc = 0; kc < 8; kc++) {
        {
            const float* Ap = A + (size_t)(row0 + lr) * lda + kc * 16 + lk;
            float4 v0 = *(const float4*)(Ap);
            float4 v1 = *(const float4*)(Ap + 4);
            AsT[lk + 0][lr] = v0.x; AsT[lk + 1][lr] = v0.y;
            AsT[lk + 2][lr] = v0.z; AsT[lk + 3][lr] = v0.w;
            AsT[lk + 4][lr] = v1.x; AsT[lk + 5][lr] = v1.y;
            AsT[lk + 6][lr] = v1.z; AsT[lk + 7][lr] = v1.w;
        }
#pragma unroll
        for (int i = 0; i < 2; i++) {
            int s   = tid + i * 256;   // 0..511 float4 units
            int wr  = s >> 5;          // 0..15
            int wc4 = s & 31;          // 0..31
            *(float4*)&Ws[wr][wc4 * 4] =
                *(const float4*)(W + (size_t)(kc * 16 + wr) * 128 + wc4 * 4);
        }
        __syncthreads();

#pragma unroll
        for (int k = 0; k < 16; k++) {
            float4 a0 = *(const float4*)&AsT[k][tr * 8];
            float4 a1 = *(const float4*)&AsT[k][tr * 8 + 4];
            ulonglong2 w01 = *(const ulonglong2*)&Ws[k][tc * 8];
            ulonglong2 w23 = *(const ulonglong2*)&Ws[k][tc * 8 + 4];
            float av[8] = {a0.x, a0.y, a0.z, a0.w, a1.x, a1.y, a1.z, a1.w};
#pragma unroll
            for (int i = 0; i < 8; i++) {
                unsigned long long aa = pack2(av[i], av[i]);
                ffma2(acc[i][0], aa, w01.x);
                ffma2(acc[i][1], aa, w01.y);
                ffma2(acc[i][2], aa, w23.x);
                ffma2(acc[i][3], aa, w23.y);
            }
        }
        __syncthreads();
    }
#pragma unroll
    for (int i = 0; i < 8; i++) {
        float* o = d_m + (size_t)(row0 + tr * 8 + i) * 128 + tc * 8;
        ulonglong2 u0, u1;
        u0.x = acc[i][0]; u0.y = acc[i][1];
        u1.x = acc[i][2]; u1.y = acc[i][3];
        *(ulonglong2*)o       = u0;
        *(ulonglong2*)(o + 4) = u1;
    }
}

// agg[dst] = relu(sum_{src in list(dst)} m[src] + b). Warp per node, float4
// per lane, shfl-broadcast indices, 4 independent accumulators (MLP=4).
__global__ void k_agg(const float* __restrict__ bias, int chBase) {
    __shared__ float bsum[8][128];
    __shared__ float bsq [8][128];
    int wid = threadIdx.x >> 5, lane = threadIdx.x & 31;
    int warpG = blockIdx.x * 8 + wid;
    int totW  = gridDim.x * 8;
    float4 bv = *(const float4*)(bias + lane * 4);
    const float4* m4 = (const float4*)d_m;
    float s0 = 0, s1 = 0, s2 = 0, s3 = 0, q0 = 0, q1 = 0, q2 = 0, q3 = 0;

    for (int node = warpG; node < NN; node += totW) {
        int raw = d_in_cnt[node];
        int cnt = raw < SLOTS ? raw : SLOTS;
        const int* lst = d_in_list + (size_t)node * SLOTS;
        int i0 = (lane < cnt)      ? lst[lane]      : 0;
        int i1 = (32 + lane < cnt) ? lst[32 + lane] : 0;

        float4 a0 = {0,0,0,0}, a1 = {0,0,0,0}, a2 = {0,0,0,0}, a3 = {0,0,0,0};
        int c1 = cnt < 32 ? cnt : 32;
        int j = 0;
        for (; j + 4 <= c1; j += 4) {
            int t0 = __shfl_sync(0xffffffffu, i0, j);
            int t1 = __shfl_sync(0xffffffffu, i0, j + 1);
            int t2 = __shfl_sync(0xffffffffu, i0, j + 2);
            int t3 = __shfl_sync(0xffffffffu, i0, j + 3);
            float4 v0 = m4[(size_t)t0 * 32 + lane];
            float4 v1 = m4[(size_t)t1 * 32 + lane];
            float4 v2 = m4[(size_t)t2 * 32 + lane];
            float4 v3 = m4[(size_t)t3 * 32 + lane];
            a0.x += v0.x; a0.y += v0.y; a0.z += v0.z; a0.w += v0.w;
            a1.x += v1.x; a1.y += v1.y; a1.z += v1.z; a1.w += v1.w;
            a2.x += v2.x; a2.y += v2.y; a2.z += v2.z; a2.w += v2.w;
            a3.x += v3.x; a3.y += v3.y; a3.z += v3.z; a3.w += v3.w;
        }
        for (; j < c1; j++) {
            int t0 = __shfl_sync(0xffffffffu, i0, j);
            float4 v0 = m4[(size_t)t0 * 32 + lane];
            a0.x += v0.x; a0.y += v0.y; a0.z += v0.z; a0.w += v0.w;
        }
        for (int j2 = 32; j2 < cnt; j2++) {
            int t0 = __shfl_sync(0xffffffffu, i1, j2 - 32);
            float4 v0 = m4[(size_t)t0 * 32 + lane];
            a1.x += v0.x; a1.y += v0.y; a1.z += v0.z; a1.w += v0.w;
        }
        float4 o;
        o.x = fmaxf(a0.x + a1.x + a2.x + a3.x + bv.x, 0.f);
        o.y = fmaxf(a0.y + a1.y + a2.y + a3.y + bv.y, 0.f);
        o.z = fmaxf(a0.z + a1.z + a2.z + a3.z + bv.z, 0.f);
        o.w = fmaxf(a0.w + a1.w + a2.w + a3.w + bv.w, 0.f);
        *(float4*)(d_X + (size_t)node * C3 + chBase + lane * 4) = o;
        s0 += o.x; s1 += o.y; s2 += o.z; s3 += o.w;
        q0 = fmaf(o.x, o.x, q0); q1 = fmaf(o.y, o.y, q1);
        q2 = fmaf(o.z, o.z, q2); q3 = fmaf(o.w, o.w, q3);
    }
    bsum[wid][lane * 4 + 0] = s0; bsum[wid][lane * 4 + 1] = s1;
    bsum[wid][lane * 4 + 2] = s2; bsum[wid][lane * 4 + 3] = s3;
    bsq [wid][lane * 4 + 0] = q0; bsq [wid][lane * 4 + 1] = q1;
    bsq [wid][lane * 4 + 2] = q2; bsq [wid][lane * 4 + 3] = q3;
    __syncthreads();
    if (threadIdx.x < 128) {
        int ch = threadIdx.x;
        float ts = 0.f, tq = 0.f;
#pragma unroll
        for (int w = 0; w < 8; w++) { ts += bsum[w][ch]; tq += bsq[w][ch]; }
        atomicAdd(&d_csum [chBase + ch], ts);
        atomicAdd(&d_csum2[chBase + ch], tq);
    }
}

// BN affine + centroid norms
__global__ void k_bn(const float* __restrict__ gamma, const float* __restrict__ beta,
                     const float* __restrict__ kmat) {
    int t = threadIdx.x;
    if (t < C3) {
        float mu  = d_csum [t] * (1.f / NN);
        float var = d_csum2[t] * (1.f / NN) - mu * mu;
        float a   = gamma[t] * rsqrtf(var + 1e-5f);
        d_a[t]  = a;
        d_bb[t] = beta[t] - mu * a;
    }
    int wid = t >> 5, lane = t & 31;
    if (wid < NCENT) {
        float s = 0.f;
        for (int c = lane; c < C3; c += 32) {
            float v = kmat[wid * C3 + c];
            s = fmaf(v, v, s);
        }
#pragma unroll
        for (int off = 16; off; off >>= 1) s += __shfl_xor_sync(0xffffffffu, s, off);
        if (lane == 0) d_knorm[wid] = s;
    }
}

// per-node soft assignment S (sum over heads of normalized t-dist)
__global__ void k_dist(const float* __restrict__ kmat) {
    __shared__ float k2s[NCENT * C3];
    __shared__ float a_s[C3], bb_s[C3];
    __shared__ float kn_s[NCENT];
    for (int i = threadIdx.x; i < NCENT * C3; i += 256) k2s[i] = kmat[i];
    for (int i = threadIdx.x; i < C3; i += 256) { a_s[i] = d_a[i]; bb_s[i] = d_bb[i]; }
    if (threadIdx.x < NCENT) kn_s[threadIdx.x] = d_knorm[threadIdx.x];
    __syncthreads();

    int wid = threadIdx.x >> 5, lane = threadIdx.x & 31;
    int warpG = blockIdx.x * 8 + wid;
    int totW  = gridDim.x * 8;

    float av[12], bv[12];
#pragma unroll
    for (int u = 0; u < 12; u++) {
        av[u] = a_s [lane * 12 + u];
        bv[u] = bb_s[lane * 12 + u];
    }

    for (int node = warpG; node < NN; node += totW) {
        const float* xr = d_X + (size_t)node * C3 + lane * 12;
        float xn[12];
#pragma unroll
        for (int u = 0; u < 12; u++) xn[u] = fmaf(xr[u], av[u], bv[u]);

        float red[16];
        float nrm = 0.f;
#pragma unroll
        for (int u = 0; u < 12; u++) nrm = fmaf(xn[u], xn[u], nrm);
        red[15] = nrm;
#pragma unroll
        for (int j = 0; j < NCENT; j++) {
            const float* kr = k2s + j * C3 + lane * 12;
            float d = 0.f;
#pragma unroll
            for (int u = 0; u < 12; u++) d = fmaf(kr[u], xn[u], d);
            red[j] = d;
        }
#pragma unroll
        for (int off = 16; off; off >>= 1)
#pragma unroll
            for (int r = 0; r < 16; r++)
                red[r] += __shfl_xor_sync(0xffffffffu, red[r], off);

        if (lane == 0) {
            float nt = red[15];
            float S0 = 0.f, S1 = 0.f, S2 = 0.f;
#pragma unroll
            for (int h = 0; h < NHEAD; h++) {
                float dd[3];
#pragma unroll
                for (int kk = 0; kk < 3; kk++) {
                    int j = h * 3 + kk;
                    float d2 = fmaxf(kn_s[j] + nt - 2.f * red[j], 0.f);
                    dd[kk] = 1.f / (1.f + d2);
                }
                float inv = 1.f / (dd[0] + dd[1] + dd[2]);
                S0 += dd[0] * inv; S1 += dd[1] * inv; S2 += dd[2] * inv;
            }
            float* o = d_Sf + (size_t)node * 4;
            o[0] = S0; o[1] = S1; o[2] = S2; o[3] = 0.f;
        }
    }
}

// Sagg gather (by src), deg, softmax, argmax, loss contributions. y is int32.
__global__ void k_S2(const int* __restrict__ y) {
    __shared__ float rs[5][256];
    int i = blockIdx.x * 256 + threadIdx.x;
    float sl = 0.f, c0 = 0.f, c1 = 0.f, A0 = 0.f, A1 = 0.f;
    {
        int oc  = d_out_cnt[i];
        int cnt = oc < SLOTS ? oc : SLOTS;
        const int* lst = d_out_list + (size_t)i * SLOTS;
        const float4* Sf4 = (const float4*)d_Sf;
        float r0 = 0.f, r1 = 0.f, r2 = 0.f;
        for (int j = 0; j < cnt; j++) {
            float4 s = Sf4[lst[j]];
            r0 += s.x; r1 += s.y; r2 += s.z;
        }
        int ic = d_in_cnt[i];
        float deg = 0.5f * (float)(oc + ic);
        if (deg == 0.f) deg = 1.f;
        float inv = 1.f / deg;
        r0 *= inv; r1 *= inv; r2 *= inv;
        int am = 0; float mx = r0;
        if (r1 > mx) { am = 1; mx = r1; }
        if (r2 > mx) { am = 2; mx = r2; }
        float val = 1.f / (expf(r0 - mx) + expf(r1 - mx) + expf(r2 - mx));
        d_amax[i] = am;
        d_val[i]  = val;
        if (am < 2) {
            sl = val;
            int yb = y[i >> 9];
            float ce = log1pf(expf(val)) - (yb == am ? val : 0.f);
            if (yb == 0) { c0 = 1.f; A0 = ce; } else { c1 = 1.f; A1 = ce; }
        }
    }
    int t = threadIdx.x;
    rs[0][t] = sl; rs[1][t] = c0; rs[2][t] = c1; rs[3][t] = A0; rs[4][t] = A1;
    __syncthreads();
    for (int s = 128; s > 0; s >>= 1) {
        if (t < s) {
#pragma unroll
            for (int r = 0; r < 5; r++) rs[r][t] += rs[r][t + s];
        }
        __syncthreads();
    }
    if (t < 5) atomicAdd(&d_scal[t], rs[t][0]);
}

// per-graph pooling xp[k,c] = sum_n Sfin * Xn, then @ lin_pool_W -> outx[b,2,16]
__global__ void k_pool(const float* __restrict__ Wp) {
    int b = blockIdx.x, t = threadIdx.x;
    __shared__ float vals[512];
    __shared__ int   ams[512];
    __shared__ float xp[2][C3];
    for (int n = t; n < 512; n += 384) {
        vals[n] = d_val [b * 512 + n];
        ams[n]  = d_amax[b * 512 + n];
    }
    __syncthreads();
    float ac = d_a[t], bc = d_bb[t];
    float acc0 = 0.f, acc1 = 0.f;
    const float* Xb = d_X + (size_t)b * 512 * C3 + t;
    for (int n = 0; n < 512; n++) {
        float x  = Xb[(size_t)n * C3];
        float v  = vals[n];
        int   am = ams[n];
        float xn = fmaf(x, ac, bc);
        if (am == 0)      acc0 = fmaf(v, xn, acc0);
        else if (am == 1) acc1 = fmaf(v, xn, acc1);
    }
    xp[0][t] = acc0; xp[1][t] = acc1;
    __syncthreads();
    if (t < 32) {
        int kk = t >> 4, o = t & 15;
        float s = 0.f;
        for (int c = 0; c < C3; c++) s = fmaf(xp[kk][c], Wp[c * 16 + o], s);
        d_outx[b * 32 + kk * 16 + o] = s;
    }
}

// classification head: relu(xf@W1+b1) @ W2 + b2, log_softmax
__global__ void k_head(const float* __restrict__ W1, const float* __restrict__ b1,
                       const float* __restrict__ W2, const float* __restrict__ b2,
                       float* __restrict__ out) {
    int b = blockIdx.x, t = threadIdx.x;
    __shared__ float xf[32];
    __shared__ float h[128];
    __shared__ float lg[2];
    if (t < 32) xf[t] = d_outx[b * 32 + t];
    __syncthreads();
    float acc = b1[t];
#pragma unroll
    for (int i = 0; i < 32; i++) acc = fmaf(xf[i], W1[i * 128 + t], acc);
    h[t] = fmaxf(acc, 0.f);
    __syncthreads();
    if (t < 64) {
        int c = t >> 5, l = t & 31;
        float p = 0.f;
        for (int j = l; j < 128; j += 32) p = fmaf(h[j], W2[j * 2 + c], p);
#pragma unroll
        for (int off = 16; off; off >>= 1) p += __shfl_xor_sync(0xffffffffu, p, off);
        if (l == 0) lg[c] = p + b2[c];
    }
    __syncthreads();
    if (t == 0) {
        float m   = fmaxf(lg[0], lg[1]);
        float lse = m + logf(expf(lg[0] - m) + expf(lg[1] - m));
        out[b * 2 + 0] = lg[0] - lse;
        out[b * 2 + 1] = lg[1] - lse;
    }
}

__global__ void k_loss(float* __restrict__ out, int idx) {
    float sl = d_scal[0], c0 = d_scal[1], c1 = d_scal[2];
    float A0 = d_scal[3], A1 = d_scal[4];
    float bc0 = 1.f + c0, bc1 = 1.f + c1;
    float wm  = fmaxf(bc0, bc1);
    float w0  = wm / (bc0 + 0.001f), w1 = wm / (bc1 + 0.001f);
    float den = fmaxf(w0 * c0 + w1 * c1, 1e-12f);
    float cel = (w0 * A0 + w1 * A1) / den;
    out[idx] = 10.f * cel + 0.01f * (sl * (1.f / 128.f));
}

// ---------------- launch ----------------
extern "C" void kernel_launch(void* const* d_in, const int* in_sizes, int n_in,
                              void* d_out, int out_size) {
    const float* x     = (const float*)d_in[0];
    const int*   ei    = (const int*)d_in[1];
    const int*   y     = (const int*)d_in[2];
    const float* W1    = (const float*)d_in[3];
    const float* b1    = (const float*)d_in[4];
    const float* W2    = (const float*)d_in[5];
    const float* b2    = (const float*)d_in[6];
    const float* W3    = (const float*)d_in[7];
    const float* b3    = (const float*)d_in[8];
    const float* gamma = (const float*)d_in[9];
    const float* beta  = (const float*)d_in[10];
    const float* kmat  = (const float*)d_in[11];
    const float* Wp    = (const float*)d_in[12];
    const float* l1W   = (const float*)d_in[13];
    const float* l1b   = (const float*)d_in[14];
    const float* l2W   = (const float*)d_in[15];
    const float* l2b   = (const float*)d_in[16];
    float* out = (float*)d_out;

    // Launch order chosen so ncu's captured launch (#6, -s 5 -c 1) is gemm2.
    k_zero1<<<256, 256>>>();                 // 1
    k_zero2<<<2, 256>>>();                   // 2
    k_fill<<<2048, 256>>>(ei);               // 3

    k_gemm<<<512, 256>>>(x, 0, W1);          // 4
    k_agg<<<2048, 256>>>(b1, 0);             // 5
    k_gemm<<<512, 256>>>(x, 1, W2);          // 6  <- ncu captures this
    k_agg<<<2048, 256>>>(b2, 128);           // 7
    k_gemm<<<512, 256>>>(x, 2, W3);          // 8
    k_agg<<<2048, 256>>>(b3, 256);           // 9

    k_bn<<<1, 512>>>(gamma, beta, kmat);     // 10
    k_dist<<<2048, 256>>>(kmat);             // 11
    k_S2<<<256, 256>>>(y);                   // 12
    k_pool<<<128, 384>>>(Wp);                // 13
    k_head<<<128, 128>>>(l1W, l1b, l2W, l2b, out);  // 14
    k_loss<<<1, 1>>>(out, out_size - 1);     // 15
}

// round 8
// speedup vs baseline: 1.3299x; 1.0474x over previous
#include <cuda_runtime.h>
#include <cstdint>

#define NN    65536          // B*N nodes
#define EDG   1048576        // B*EPER edges
#define SLOTS 64             // max adjacency slots per node
#define C3    384
#define NHEAD 5
#define NCENT 15             // HEADS*KC

// ---------------- scratch (static __device__, no allocations) ----------------
__device__ int   d_in_cnt[NN];
__device__ int   d_out_cnt[NN];
__device__ int   d_in_list[NN * SLOTS];
__device__ int   d_out_list[NN * SLOTS];
__device__ float d_m[(size_t)NN * 128];
__device__ float d_X[(size_t)NN * C3];
__device__ float d_Sf[(size_t)NN * 4];
__device__ float d_val[NN];
__device__ int   d_amax[NN];
__device__ float d_outx[128 * 32];
__device__ float d_csum[C3], d_csum2[C3];
__device__ float d_a[C3], d_bb[C3];
__device__ float d_knorm[NCENT];
__device__ float d_scal[8];

// ---------------- packed f32x2 helpers (Blackwell FFMA2) ----------------
__device__ __forceinline__ unsigned long long pack2(float lo, float hi) {
    unsigned long long r;
    asm("mov.b64 %0, {%1, %2};" : "=l"(r) : "f"(lo), "f"(hi));
    return r;
}
__device__ __forceinline__ void ffma2(unsigned long long& acc,
                                      unsigned long long a, unsigned long long b) {
    asm("fma.rn.f32x2 %0, %1, %2, %0;" : "+l"(acc) : "l"(a), "l"(b));
}
// ---------------- cp.async helpers ----------------
__device__ __forceinline__ uint32_t su32(const void* p) {
    return (uint32_t)__cvta_generic_to_shared(p);
}
__device__ __forceinline__ void cpa16(uint32_t s, const void* g) {
    asm volatile("cp.async.cg.shared.global [%0], [%1], 16;" :: "r"(s), "l"(g));
}
#define CP_COMMIT() asm volatile("cp.async.commit_group;")
#define CP_WAIT(N)  asm volatile("cp.async.wait_group %0;" :: "n"(N))

// ---------------- kernels ----------------
__global__ void k_zero1() {
    int i = blockIdx.x * 256 + threadIdx.x;
    if (i < NN) { d_in_cnt[i] = 0; d_out_cnt[i] = 0; }
}
__global__ void k_zero2() {
    int i = blockIdx.x * 256 + threadIdx.x;
    if (i < C3) { d_csum[i] = 0.f; d_csum2[i] = 0.f; }
    if (i < 8)  d_scal[i] = 0.f;
}

__global__ void k_fill(const int* __restrict__ ei) {
    const int* src = ei;
    const int* dst = ei + EDG;
    for (int e = blockIdx.x * blockDim.x + threadIdx.x; e < EDG;
         e += gridDim.x * blockDim.x) {
        int s = src[e] & (NN - 1);
        int d = dst[e] & (NN - 1);
        int sl = atomicAdd(&d_in_cnt[d], 1);
        if (sl < SLOTS) d_in_list[d * SLOTS + sl] = s;
        int s2 = atomicAdd(&d_out_cnt[s], 1);
        if (s2 < SLOTS) d_out_list[s * SLOTS + s2] = d;
    }
}

// m = A(65536x128) @ W(128x128). BM=128, BN=128, BK=16, 8x8 FFMA2 tile,
// cp.async double-buffered tiles (LDG overlapped with compute).
// A smem layout: Asb[buf][g*128 + row] = float4 of k=4g..4g+3.
__global__ void __launch_bounds__(256, 2)
k_gemm(const float* __restrict__ Aext, int mode, const float* __restrict__ W) {
    __shared__ float4 Asb[2][4 * 128];
    __shared__ float  Wsb[2][16 * 132];
    const float* A;
    int lda;
    if (mode == 0)      { A = Aext;      lda = 128; }
    else if (mode == 1) { A = d_X;       lda = C3;  }
    else                { A = d_X + 128; lda = C3;  }

    int tid  = threadIdx.x;
    int row0 = blockIdx.x * 128;
    int tr   = tid >> 4;     // 0..15 -> rows tr*8..tr*8+7
    int tc   = tid & 15;     // 0..15 -> cols tc*8..tc*8+7

    // load mappings
    int ra  = tid & 127;     // A row
    int ga  = tid >> 7;      // A k-group 0..1 (second cp handles ga+2)
    int wr0 = tid >> 5;      // W row 0..7 (second cp handles +8)
    int wc0 = (tid & 31) * 4;

    const float* Arow = A + (size_t)(row0 + ra) * lda + ga * 4;

    unsigned long long acc[8][4];
#pragma unroll
    for (int i = 0; i < 8; i++)
#pragma unroll
        for (int j = 0; j < 4; j++) acc[i][j] = 0ull;

#define ISSUE(kc, buf)                                                        \
    do {                                                                      \
        const float* g0 = Arow + (kc) * 16;                                   \
        cpa16(su32(&Asb[buf][ga * 128 + ra]), g0);                            \
        cpa16(su32(&Asb[buf][(ga + 2) * 128 + ra]), g0 + 8);                  \
        cpa16(su32(&Wsb[buf][wr0 * 132 + wc0]),                               \
              W + (size_t)((kc) * 16 + wr0) * 128 + wc0);                     \
        cpa16(su32(&Wsb[buf][(wr0 + 8) * 132 + wc0]),                         \
              W + (size_t)((kc) * 16 + wr0 + 8) * 128 + wc0);                 \
        CP_COMMIT();                                                          \
    } while (0)

    ISSUE(0, 0);

#pragma unroll
    for (int kc = 0; kc < 8; kc++) {
        if (kc < 7) { ISSUE(kc + 1, (kc + 1) & 1); CP_WAIT(1); }
        else        { CP_WAIT(0); }
        __syncthreads();

        const float4* ab = Asb[kc & 1];
        const float*  wb = Wsb[kc & 1];
#pragma unroll
        for (int g = 0; g < 4; g++) {
            float4 a[8];
#pragma unroll
            for (int i = 0; i < 8; i++) a[i] = ab[g * 128 + tr * 8 + i];
#pragma unroll
            for (int k2 = 0; k2 < 4; k2++) {
                const float* wrow = wb + (g * 4 + k2) * 132 + tc * 8;
                ulonglong2 w01 = *(const ulonglong2*)wrow;
                ulonglong2 w23 = *(const ulonglong2*)(wrow + 4);
#pragma unroll
                for (int i = 0; i < 8; i++) {
                    float av = (k2 == 0) ? a[i].x : (k2 == 1) ? a[i].y
                             : (k2 == 2) ? a[i].z : a[i].w;
                    unsigned long long aa = pack2(av, av);
                    ffma2(acc[i][0], aa, w01.x);
                    ffma2(acc[i][1], aa, w01.y);
                    ffma2(acc[i][2], aa, w23.x);
                    ffma2(acc[i][3], aa, w23.y);
                }
            }
        }
        __syncthreads();
    }
#undef ISSUE

#pragma unroll
    for (int i = 0; i < 8; i++) {
        float* o = d_m + (size_t)(row0 + tr * 8 + i) * 128 + tc * 8;
        ulonglong2 u0, u1;
        u0.x = acc[i][0]; u0.y = acc[i][1];
        u1.x = acc[i][2]; u1.y = acc[i][3];
        *(ulonglong2*)o       = u0;
        *(ulonglong2*)(o + 4) = u1;
    }
}

// agg[dst] = relu(sum_{src in list(dst)} m[src] + b). Warp per node.
__global__ void k_agg(const float* __restrict__ bias, int chBase) {
    __shared__ float bsum[8][128];
    __shared__ float bsq [8][128];
    int wid = threadIdx.x >> 5, lane = threadIdx.x & 31;
    int warpG = blockIdx.x * 8 + wid;
    int totW  = gridDim.x * 8;
    float4 bv = *(const float4*)(bias + lane * 4);
    const float4* m4 = (const float4*)d_m;
    float s0 = 0, s1 = 0, s2 = 0, s3 = 0, q0 = 0, q1 = 0, q2 = 0, q3 = 0;

    for (int node = warpG; node < NN; node += totW) {
        int raw = d_in_cnt[node];
        int cnt = raw < SLOTS ? raw : SLOTS;
        const int* lst = d_in_list + (size_t)node * SLOTS;
        int i0 = (lane < cnt)      ? lst[lane]      : 0;
        int i1 = (32 + lane < cnt) ? lst[32 + lane] : 0;

        float4 a0 = {0,0,0,0}, a1 = {0,0,0,0}, a2 = {0,0,0,0}, a3 = {0,0,0,0};
        int c1 = cnt < 32 ? cnt : 32;
        int j = 0;
        for (; j + 4 <= c1; j += 4) {
            int t0 = __shfl_sync(0xffffffffu, i0, j);
            int t1 = __shfl_sync(0xffffffffu, i0, j + 1);
            int t2 = __shfl_sync(0xffffffffu, i0, j + 2);
            int t3 = __shfl_sync(0xffffffffu, i0, j + 3);
            float4 v0 = m4[(size_t)t0 * 32 + lane];
            float4 v1 = m4[(size_t)t1 * 32 + lane];
            float4 v2 = m4[(size_t)t2 * 32 + lane];
            float4 v3 = m4[(size_t)t3 * 32 + lane];
            a0.x += v0.x; a0.y += v0.y; a0.z += v0.z; a0.w += v0.w;
            a1.x += v1.x; a1.y += v1.y; a1.z += v1.z; a1.w += v1.w;
            a2.x += v2.x; a2.y += v2.y; a2.z += v2.z; a2.w += v2.w;
            a3.x += v3.x; a3.y += v3.y; a3.z += v3.z; a3.w += v3.w;
        }
        for (; j < c1; j++) {
            int t0 = __shfl_sync(0xffffffffu, i0, j);
            float4 v0 = m4[(size_t)t0 * 32 + lane];
            a0.x += v0.x; a0.y += v0.y; a0.z += v0.z; a0.w += v0.w;
        }
        for (int j2 = 32; j2 < cnt; j2++) {
            int t0 = __shfl_sync(0xffffffffu, i1, j2 - 32);
            float4 v0 = m4[(size_t)t0 * 32 + lane];
            a1.x += v0.x; a1.y += v0.y; a1.z += v0.z; a1.w += v0.w;
        }
        float4 o;
        o.x = fmaxf(a0.x + a1.x + a2.x + a3.x + bv.x, 0.f);
        o.y = fmaxf(a0.y + a1.y + a2.y + a3.y + bv.y, 0.f);
        o.z = fmaxf(a0.z + a1.z + a2.z + a3.z + bv.z, 0.f);
        o.w = fmaxf(a0.w + a1.w + a2.w + a3.w + bv.w, 0.f);
        *(float4*)(d_X + (size_t)node * C3 + chBase + lane * 4) = o;
        s0 += o.x; s1 += o.y; s2 += o.z; s3 += o.w;
        q0 = fmaf(o.x, o.x, q0); q1 = fmaf(o.y, o.y, q1);
        q2 = fmaf(o.z, o.z, q2); q3 = fmaf(o.w, o.w, q3);
    }
    bsum[wid][lane * 4 + 0] = s0; bsum[wid][lane * 4 + 1] = s1;
    bsum[wid][lane * 4 + 2] = s2; bsum[wid][lane * 4 + 3] = s3;
    bsq [wid][lane * 4 + 0] = q0; bsq [wid][lane * 4 + 1] = q1;
    bsq [wid][lane * 4 + 2] = q2; bsq [wid][lane * 4 + 3] = q3;
    __syncthreads();
    if (threadIdx.x < 128) {
        int ch = threadIdx.x;
        float ts = 0.f, tq = 0.f;
#pragma unroll
        for (int w = 0; w < 8; w++) { ts += bsum[w][ch]; tq += bsq[w][ch]; }
        atomicAdd(&d_csum [chBase + ch], ts);
        atomicAdd(&d_csum2[chBase + ch], tq);
    }
}

// BN affine + centroid norms
__global__ void k_bn(const float* __restrict__ gamma, const float* __restrict__ beta,
                     const float* __restrict__ kmat) {
    int t = threadIdx.x;
    if (t < C3) {
        float mu  = d_csum [t] * (1.f / NN);
        float var = d_csum2[t] * (1.f / NN) - mu * mu;
        float a   = gamma[t] * rsqrtf(var + 1e-5f);
        d_a[t]  = a;
        d_bb[t] = beta[t] - mu * a;
    }
    int wid = t >> 5, lane = t & 31;
    if (wid < NCENT) {
        float s = 0.f;
        for (int c = lane; c < C3; c += 32) {
            float v = kmat[wid * C3 + c];
            s = fmaf(v, v, s);
        }
#pragma unroll
        for (int off = 16; off; off >>= 1) s += __shfl_xor_sync(0xffffffffu, s, off);
        if (lane == 0) d_knorm[wid] = s;
    }
}

// per-node soft assignment S (sum over heads of normalized t-dist)
__global__ void k_dist(const float* __restrict__ kmat) {
    __shared__ float k2s[NCENT * C3];
    __shared__ float a_s[C3], bb_s[C3];
    __shared__ float kn_s[NCENT];
    for (int i = threadIdx.x; i < NCENT * C3; i += 256) k2s[i] = kmat[i];
    for (int i = threadIdx.x; i < C3; i += 256) { a_s[i] = d_a[i]; bb_s[i] = d_bb[i]; }
    if (threadIdx.x < NCENT) kn_s[threadIdx.x] = d_knorm[threadIdx.x];
    __syncthreads();

    int wid = threadIdx.x >> 5, lane = threadIdx.x & 31;
    int warpG = blockIdx.x * 8 + wid;
    int totW  = gridDim.x * 8;

    float av[12], bv[12];
#pragma unroll
    for (int u = 0; u < 12; u++) {
        av[u] = a_s [lane * 12 + u];
        bv[u] = bb_s[lane * 12 + u];
    }

    for (int node = warpG; node < NN; node += totW) {
        const float* xr = d_X + (size_t)node * C3 + lane * 12;
        float xn[12];
#pragma unroll
        for (int u = 0; u < 12; u++) xn[u] = fmaf(xr[u], av[u], bv[u]);

        float red[16];
        float nrm = 0.f;
#pragma unroll
        for (int u = 0; u < 12; u++) nrm = fmaf(xn[u], xn[u], nrm);
        red[15] = nrm;
#pragma unroll
        for (int j = 0; j < NCENT; j++) {
            const float* kr = k2s + j * C3 + lane * 12;
            float d = 0.f;
#pragma unroll
            for (int u = 0; u < 12; u++) d = fmaf(kr[u], xn[u], d);
            red[j] = d;
        }
#pragma unroll
        for (int off = 16; off; off >>= 1)
#pragma unroll
            for (int r = 0; r < 16; r++)
                red[r] += __shfl_xor_sync(0xffffffffu, red[r], off);

        if (lane == 0) {
            float nt = red[15];
            float S0 = 0.f, S1 = 0.f, S2 = 0.f;
#pragma unroll
            for (int h = 0; h < NHEAD; h++) {
                float dd[3];
#pragma unroll
                for (int kk = 0; kk < 3; kk++) {
                    int j = h * 3 + kk;
                    float d2 = fmaxf(kn_s[j] + nt - 2.f * red[j], 0.f);
                    dd[kk] = 1.f / (1.f + d2);
                }
                float inv = 1.f / (dd[0] + dd[1] + dd[2]);
                S0 += dd[0] * inv; S1 += dd[1] * inv; S2 += dd[2] * inv;
            }
            float* o = d_Sf + (size_t)node * 4;
            o[0] = S0; o[1] = S1; o[2] = S2; o[3] = 0.f;
        }
    }
}

// Sagg gather (by src), deg, softmax, argmax, loss contributions.
__global__ void k_S2(const int* __restrict__ y) {
    __shared__ float rs[5][256];
    int i = blockIdx.x * 256 + threadIdx.x;
    float sl = 0.f, c0 = 0.f, c1 = 0.f, A0 = 0.f, A1 = 0.f;
    {
        int oc  = d_out_cnt[i];
        int cnt = oc < SLOTS ? oc : SLOTS;
        const int* lst = d_out_list + (size_t)i * SLOTS;
        const float4* Sf4 = (const float4*)d_Sf;
        float r0 = 0.f, r1 = 0.f, r2 = 0.f;
        for (int j = 0; j < cnt; j++) {
            float4 s = Sf4[lst[j]];
            r0 += s.x; r1 += s.y; r2 += s.z;
        }
        int ic = d_in_cnt[i];
        float deg = 0.5f * (float)(oc + ic);
        if (deg == 0.f) deg = 1.f;
        float inv = 1.f / deg;
        r0 *= inv; r1 *= inv; r2 *= inv;
        int am = 0; float mx = r0;
        if (r1 > mx) { am = 1; mx = r1; }
        if (r2 > mx) { am = 2; mx = r2; }
        float val = 1.f / (expf(r0 - mx) + expf(r1 - mx) + expf(r2 - mx));
        d_amax[i] = am;
        d_val[i]  = val;
        if (am < 2) {
            sl = val;
            int yb = y[i >> 9];
            float ce = log1pf(expf(val)) - (yb == am ? val : 0.f);
            if (yb == 0) { c0 = 1.f; A0 = ce; } else { c1 = 1.f; A1 = ce; }
        }
    }
    int t = threadIdx.x;
    rs[0][t] = sl; rs[1][t] = c0; rs[2][t] = c1; rs[3][t] = A0; rs[4][t] = A1;
    __syncthreads();
    for (int s = 128; s > 0; s >>= 1) {
        if (t < s) {
#pragma unroll
            for (int r = 0; r < 5; r++) rs[r][t] += rs[r][t + s];
        }
        __syncthreads();
    }
    if (t < 5) atomicAdd(&d_scal[t], rs[t][0]);
}

// per-graph pooling
__global__ void k_pool(const float* __restrict__ Wp) {
    int b = blockIdx.x, t = threadIdx.x;
    __shared__ float vals[512];
    __shared__ int   ams[512];
    __shared__ float xp[2][C3];
    for (int n = t; n < 512; n += 384) {
        vals[n] = d_val [b * 512 + n];
        ams[n]  = d_amax[b * 512 + n];
    }
    __syncthreads();
    float ac = d_a[t], bc = d_bb[t];
    float acc0 = 0.f, acc1 = 0.f;
    const float* Xb = d_X + (size_t)b * 512 * C3 + t;
    for (int n = 0; n < 512; n++) {
        float x  = Xb[(size_t)n * C3];
        float v  = vals[n];
        int   am = ams[n];
        float xn = fmaf(x, ac, bc);
        if (am == 0)      acc0 = fmaf(v, xn, acc0);
        else if (am == 1) acc1 = fmaf(v, xn, acc1);
    }
    xp[0][t] = acc0; xp[1][t] = acc1;
    __syncthreads();
    if (t < 32) {
        int kk = t >> 4, o = t & 15;
        float s = 0.f;
        for (int c = 0; c < C3; c++) s = fmaf(xp[kk][c], Wp[c * 16 + o], s);
        d_outx[b * 32 + kk * 16 + o] = s;
    }
}

// classification head
__global__ void k_head(const float* __restrict__ W1, const float* __restrict__ b1,
                       const float* __restrict__ W2, const float* __restrict__ b2,
                       float* __restrict__ out) {
    int b = blockIdx.x, t = threadIdx.x;
    __shared__ float xf[32];
    __shared__ float h[128];
    __shared__ float lg[2];
    if (t < 32) xf[t] = d_outx[b * 32 + t];
    __syncthreads();
    float acc = b1[t];
#pragma unroll
    for (int i = 0; i < 32; i++) acc = fmaf(xf[i], W1[i * 128 + t], acc);
    h[t] = fmaxf(acc, 0.f);
    __syncthreads();
    if (t < 64) {
        int c = t >> 5, l = t & 31;
        float p = 0.f;
        for (int j = l; j < 128; j += 32) p = fmaf(h[j], W2[j * 2 + c], p);
#pragma unroll
        for (int off = 16; off; off >>= 1) p += __shfl_xor_sync(0xffffffffu, p, off);
        if (l == 0) lg[c] = p + b2[c];
    }
    __syncthreads();
    if (t == 0) {
        float m   = fmaxf(lg[0], lg[1]);
        float lse = m + logf(expf(lg[0] - m) + expf(lg[1] - m));
        out[b * 2 + 0] = lg[0] - lse;
        out[b * 2 + 1] = lg[1] - lse;
    }
}

__global__ void k_loss(float* __restrict__ out, int idx) {
    float sl = d_scal[0], c0 = d_scal[1], c1 = d_scal[2];
    float A0 = d_scal[3], A1 = d_scal[4];
    float bc0 = 1.f + c0, bc1 = 1.f + c1;
    float wm  = fmaxf(bc0, bc1);
    float w0  = wm / (bc0 + 0.001f), w1 = wm / (bc1 + 0.001f);
    float den = fmaxf(w0 * c0 + w1 * c1, 1e-12f);
    float cel = (w0 * A0 + w1 * A1) / den;
    out[idx] = 10.f * cel + 0.01f * (sl * (1.f / 128.f));
}

// ---------------- launch ----------------
extern "C" void kernel_launch(void* const* d_in, const int* in_sizes, int n_in,
                              void* d_out, int out_size) {
    const float* x     = (const float*)d_in[0];
    const int*   ei    = (const int*)d_in[1];
    const int*   y     = (const int*)d_in[2];
    const float* W1    = (const float*)d_in[3];
    const float* b1    = (const float*)d_in[4];
    const float* W2    = (const float*)d_in[5];
    const float* b2    = (const float*)d_in[6];
    const float* W3    = (const float*)d_in[7];
    const float* b3    = (const float*)d_in[8];
    const float* gamma = (const float*)d_in[9];
    const float* beta  = (const float*)d_in[10];
    const float* kmat  = (const float*)d_in[11];
    const float* Wp    = (const float*)d_in[12];
    const float* l1W   = (const float*)d_in[13];
    const float* l1b   = (const float*)d_in[14];
    const float* l2W   = (const float*)d_in[15];
    const float* l2b   = (const float*)d_in[16];
    float* out = (float*)d_out;

    // Launch order chosen so ncu's captured launch (#6, -s 5 -c 1) is gemm2.
    k_zero1<<<256, 256>>>();                 // 1
    k_zero2<<<2, 256>>>();                   // 2
    k_fill<<<2048, 256>>>(ei);               // 3

    k_gemm<<<512, 256>>>(x, 0, W1);          // 4
    k_agg<<<2048, 256>>>(b1, 0);             // 5
    k_gemm<<<512, 256>>>(x, 1, W2);          // 6  <- ncu captures this
    k_agg<<<2048, 256>>>(b2, 128);           // 7
    k_gemm<<<512, 256>>>(x, 2, W3);          // 8
    k_agg<<<2048, 256>>>(b3, 256);           // 9

    k_bn<<<1, 512>>>(gamma, beta, kmat);     // 10
    k_dist<<<2048, 256>>>(kmat);             // 11
    k_S2<<<256, 256>>>(y);                   // 12
    k_pool<<<128, 384>>>(Wp);                // 13
    k_head<<<128, 128>>>(l1W, l1b, l2W, l2b, out);  // 14
    k_loss<<<1, 1>>>(out, out_size - 1);     // 15
}